// round 11
// baseline (speedup 1.0000x reference)
#include <cuda_runtime.h>
#include <cuda_bf16.h>
#include <math.h>
#include <stdint.h>

// Problem shape (fixed by the dataset)
#define S_TOT 4096
#define C_TOT 64
#define F_TOT 256

// ---------------- scratch (device globals: no allocation allowed) ----------
__device__ float         g_norm[S_TOT * F_TOT];   // normalized rays r[s][f] (fp32)
__device__ float         g_len [S_TOT];           // ray lengths
__device__ unsigned      g_mu  [S_TOT];           // min over c of mu_pos (float bits)
__device__ float         g_v   [C_TOT * F_TOT];   // v_c = P_c t + q_c
__device__ float         g_cst [C_TOT];           // q.t + 0.5 tPt - b
__device__ __nv_bfloat16 g_Rhi [S_TOT * F_TOT];
__device__ __nv_bfloat16 g_Phi [C_TOT * F_TOT * F_TOT];
__device__ __nv_bfloat16 g_Plo [C_TOT * F_TOT * F_TOT];

// ---------------- PTX helpers (sm_80-era only: valid on plain sm_100) -------
__device__ __forceinline__ uint32_t smem_u32(const void* p) {
    uint32_t a;
    asm("{ .reg .u64 t; cvta.to.shared.u64 t, %1; cvt.u32.u64 %0, t; }"
        : "=r"(a) : "l"(p));
    return a;
}

__device__ __forceinline__ void ldsm_x4(uint32_t* r, uint32_t addr) {
    asm volatile("ldmatrix.sync.aligned.m8n8.x4.shared.b16 {%0,%1,%2,%3}, [%4];"
        : "=r"(r[0]), "=r"(r[1]), "=r"(r[2]), "=r"(r[3]) : "r"(addr));
}
__device__ __forceinline__ void mma16816(float* d, const uint32_t* a, const uint32_t* b) {
    asm volatile(
        "mma.sync.aligned.m16n8k16.row.col.f32.bf16.bf16.f32 "
        "{%0,%1,%2,%3}, {%4,%5,%6,%7}, {%8,%9}, {%0,%1,%2,%3};"
        : "+f"(d[0]), "+f"(d[1]), "+f"(d[2]), "+f"(d[3])
        : "r"(a[0]), "r"(a[1]), "r"(a[2]), "r"(a[3]), "r"(b[0]), "r"(b[1]));
}

#define CP_ASYNC16(dst, src) \
    asm volatile("cp.async.cg.shared.global [%0], [%1], 16;" \
                 :: "r"(dst), "l"(src) : "memory")

// ---------------- kernel 1: normalize rays, init mu, emit bf16 hi ----------
__global__ void k_norm(const float* __restrict__ zs,
                       const float* __restrict__ point)
{
    int warp = threadIdx.x >> 5;
    int lane = threadIdx.x & 31;
    int s = blockIdx.x * 8 + warp;

    const float4* z4 = (const float4*)(zs + (size_t)s * F_TOT);
    const float4* p4 = (const float4*)point;

    float4 a = z4[lane];
    float4 b = z4[lane + 32];
    float4 pa = p4[lane];
    float4 pb = p4[lane + 32];

    a.x -= pa.x; a.y -= pa.y; a.z -= pa.z; a.w -= pa.w;
    b.x -= pb.x; b.y -= pb.y; b.z -= pb.z; b.w -= pb.w;

    float ss = a.x*a.x + a.y*a.y + a.z*a.z + a.w*a.w
             + b.x*b.x + b.y*b.y + b.z*b.z + b.w*b.w;
    #pragma unroll
    for (int off = 16; off; off >>= 1)
        ss += __shfl_xor_sync(0xffffffffu, ss, off);

    float len = fmaxf(sqrtf(ss), 1e-12f);
    float inv = 1.0f / len;
    a.x *= inv; a.y *= inv; a.z *= inv; a.w *= inv;
    b.x *= inv; b.y *= inv; b.z *= inv; b.w *= inv;

    float4* o4 = (float4*)(g_norm + (size_t)s * F_TOT);
    o4[lane]      = a;
    o4[lane + 32] = b;

    __nv_bfloat162* h2 = (__nv_bfloat162*)(g_Rhi + (size_t)s * F_TOT);
    float v[8] = {a.x, a.y, a.z, a.w, b.x, b.y, b.z, b.w};
    int base2[2] = {2 * lane, 64 + 2 * lane};
    #pragma unroll
    for (int h = 0; h < 2; h++) {
        #pragma unroll
        for (int p = 0; p < 2; p++) {
            float x = v[h*4 + p*2], y = v[h*4 + p*2 + 1];
            h2[base2[h] + p] =
                __halves2bfloat162(__float2bfloat16(x), __float2bfloat16(y));
        }
    }

    if (lane == 0) {
        g_len[s] = len;
        g_mu[s]  = 0x7f800000u;   // +inf
    }
}

// ---------------- kernel: split P into bf16 hi/lo ---------------------------
__global__ void k_cvtP(const float* __restrict__ P)
{
    size_t i = (size_t)blockIdx.x * 256 + threadIdx.x;  // float4 index
    float4 x = ((const float4*)P)[i];
    __nv_bfloat16 h0 = __float2bfloat16(x.x), h1 = __float2bfloat16(x.y);
    __nv_bfloat16 h2 = __float2bfloat16(x.z), h3 = __float2bfloat16(x.w);
    __nv_bfloat16 l0 = __float2bfloat16(x.x - __bfloat162float(h0));
    __nv_bfloat16 l1 = __float2bfloat16(x.y - __bfloat162float(h1));
    __nv_bfloat16 l2 = __float2bfloat16(x.z - __bfloat162float(h2));
    __nv_bfloat16 l3 = __float2bfloat16(x.w - __bfloat162float(h3));
    ((__nv_bfloat162*)g_Phi)[2*i]   = __halves2bfloat162(h0, h1);
    ((__nv_bfloat162*)g_Phi)[2*i+1] = __halves2bfloat162(h2, h3);
    ((__nv_bfloat162*)g_Plo)[2*i]   = __halves2bfloat162(l0, l1);
    ((__nv_bfloat162*)g_Plo)[2*i+1] = __halves2bfloat162(l2, l3);
}

// ---------------- kernel: per-constraint precompute --------------------------
__global__ void k_pre(const float* __restrict__ P,
                      const float* __restrict__ q,
                      const float* __restrict__ b,
                      const float* __restrict__ point)
{
    int c = blockIdx.x;
    int k = threadIdx.x;

    __shared__ float t_sm[F_TOT];
    __shared__ float red1[F_TOT];
    __shared__ float red2[F_TOT];

    t_sm[k] = point[k];
    __syncthreads();

    const float* Pc = P + (size_t)c * F_TOT * F_TOT;
    float v = 0.0f;
    for (int f = 0; f < F_TOT; f++)
        v += Pc[f * F_TOT + k] * t_sm[f];

    float qk = q[c * F_TOT + k];
    float tk = t_sm[k];
    red1[k] = v  * tk;
    red2[k] = qk * tk;
    __syncthreads();
    for (int off = 128; off; off >>= 1) {
        if (k < off) { red1[k] += red1[k + off]; red2[k] += red2[k + off]; }
        __syncthreads();
    }
    g_v[c * F_TOT + k] = v + qk;
    if (k == 0)
        g_cst[c] = red2[0] + 0.5f * red1[0] - b[c];
}

// ---------------- main mma.sync kernel ---------------------------------------
// PERSISTENT 2-TILE CTAs. Grid (1024): bid -> s0 = (bid&31)*128 fixed,
// c = (bid>>5)*2 + t for t in {0,1}. 512 threads = 16 warps, 2(m)x8(n),
// warp tile 64(s) x 32(f), acc[4][4][4] (64 regs). Per tile:
// W = Rhi . (Phi||Plo), 8 K=64 chunks (chunk i: k0=(i>>1)*64, B=(i&1)?Plo:Phi).
//
// A (Rhi) is smem-RESIDENT: 4 static 16KB buffers (one per k-pair), loaded
// during tile 0's even chunks only; tile 1 issues no A copies.
// B: 3 rotating 32KB buffers, slot = global_chunk % 3, distance-2 prefetch,
// wait_group 1, one barrier per chunk, carried ACROSS the tile boundary so
// tile 0's epilogue overlaps tile 1's copies.
//
// SMEM: red @0 (4KB!), A @4096 (4x16KB), B @69632 (3x32KB). Total 164KB.
// (R10 bug: red is 4KB — 128 rows x 8 cols x 4B — and overlapped A at 2048.)
#define OFF_RED 0
#define OFF_A   4096
#define OFF_B   69632
#define SMEM_MMA 167936

__global__ void __launch_bounds__(512, 1) k_mma()
{
    extern __shared__ __align__(1024) char smem[];
    uint32_t sb = smem_u32(smem);
    int tid   = threadIdx.x;
    int l     = tid & 31;
    int w     = tid >> 5;
    int wm    = w & 1;        // sample group (64 rows)
    int wn    = w >> 1;       // f group (32 cols)
    int s0    = (blockIdx.x & 31) * 128;
    int cbase = (blockIdx.x >> 5) * 2;

    // issue copies for global chunk g (0..15). tile t=g>>3, in-tile i=g&7.
    auto issue_chunk = [&](int g) {
        int i  = g & 7;
        int k0 = (i >> 1) * 64;
        if (g < 8 && !(g & 1)) {   // A pair (g>>1): static buffer, tile 0 only
            uint32_t ab = sb + OFF_A + (g >> 1) * 16384;
            #pragma unroll
            for (int it = 0; it < 2; it++) {     // 128 rows x 8 x 16B
                int idx = it * 512 + tid;
                int row = idx >> 3, u = idx & 7;
                const char* src = (const char*)(g_Rhi + (size_t)(s0 + row) * F_TOT + k0 + u * 8);
                CP_ASYNC16(ab + row * 128 + (((u ^ (row & 7))) << 4), src);
            }
        }
        int c = cbase + (g >> 3);
        const __nv_bfloat16* Bsrc = (i & 1) ? g_Plo : g_Phi;
        uint32_t bb = sb + OFF_B + (g % 3) * 32768;
        #pragma unroll
        for (int it = 0; it < 4; it++) {         // B: 256 rows x 8 x 16B
            int idx = it * 512 + tid;
            int row = idx >> 3, u = idx & 7;
            const char* src = (const char*)(Bsrc + ((size_t)c * F_TOT + row) * F_TOT + k0 + u * 8);
            CP_ASYNC16(bb + row * 128 + (((u ^ (row & 7))) << 4), src);
        }
        asm volatile("cp.async.commit_group;" ::: "memory");
    };

    issue_chunk(0);
    issue_chunk(1);

    // lane-invariant ldmatrix addressing
    int xr = l & 7;             // row & 7
    int aq = (l >> 3) & 1;      // A x4: matrices 1,3 rows +8
    int uq = (l >> 4) & 1;      // A x4: matrices 2,3 k-unit +1
    int ub = (l >> 3) & 1;      // B x4: matrices 1,3 k-unit +1
    int bg = (l >> 4) & 1;      // B x4: matrices 2,3 rows +8 (next n-tile)

    float* red = (float*)(smem + OFF_RED);

    for (int t = 0; t < 2; t++) {
        int c = cbase + t;

        float acc[4][4][4];
        #pragma unroll
        for (int mt = 0; mt < 4; mt++)
            #pragma unroll
            for (int nt = 0; nt < 4; nt++)
                #pragma unroll
                for (int j = 0; j < 4; j++)
                    acc[mt][nt][j] = 0.0f;

        for (int i = 0; i < 8; i++) {
            int g = t * 8 + i;
            if (g < 15) asm volatile("cp.async.wait_group 1;" ::: "memory");
            else        asm volatile("cp.async.wait_group 0;" ::: "memory");
            __syncthreads();
            if (g + 2 < 16) issue_chunk(g + 2);   // overlaps compute of chunk g

            uint32_t ab = sb + OFF_A + (i >> 1) * 16384;
            uint32_t bb = sb + OFF_B + (g % 3) * 32768;
            uint32_t aAddr = ab + (wm * 64 + aq * 8 + xr) * 128;   // + mt*16*128
            uint32_t bAddr = bb + (wn * 32 + bg * 8 + xr) * 128;   // + p*16*128

            #pragma unroll
            for (int ks = 0; ks < 4; ks++) {
                int u0 = ks * 2;
                uint32_t swzA = ((uint32_t)((u0 + uq) ^ xr)) << 4;
                uint32_t swzB = ((uint32_t)((u0 + ub) ^ xr)) << 4;
                uint32_t afr[4][4];
                #pragma unroll
                for (int mt = 0; mt < 4; mt++)
                    ldsm_x4(afr[mt], aAddr + mt * 2048 + swzA);
                #pragma unroll
                for (int p = 0; p < 2; p++) {
                    uint32_t bfr[4];                 // n-tiles 2p, 2p+1
                    ldsm_x4(bfr, bAddr + p * 2048 + swzB);
                    #pragma unroll
                    for (int mt = 0; mt < 4; mt++) {
                        mma16816(acc[mt][2*p],     afr[mt], bfr);
                        mma16816(acc[mt][2*p + 1], afr[mt], bfr + 2);
                    }
                }
            }
        }

        // ---- epilogue: rPr[s] = sum_f W[s,f] * (2r - rhi)[s,f] ---------------
        float part[8];
        #pragma unroll
        for (int mt = 0; mt < 4; mt++) {
            #pragma unroll
            for (int half = 0; half < 2; half++) {
                int row = wm * 64 + mt * 16 + (l >> 2) + half * 8;
                const float* rrow = g_norm + (size_t)(s0 + row) * F_TOT;
                float p = 0.0f;
                #pragma unroll
                for (int nt = 0; nt < 4; nt++) {
                    int f = wn * 32 + nt * 8 + (l & 3) * 2;
                    float2 rv = *(const float2*)(rrow + f);
                    float wx = 2.0f * rv.x - __bfloat162float(__float2bfloat16(rv.x));
                    float wy = 2.0f * rv.y - __bfloat162float(__float2bfloat16(rv.y));
                    p += acc[mt][nt][half * 2 + 0] * wx
                       + acc[mt][nt][half * 2 + 1] * wy;
                }
                part[mt * 2 + half] = p;
            }
        }
        #pragma unroll
        for (int j = 0; j < 8; j++) {
            part[j] += __shfl_xor_sync(0xffffffffu, part[j], 1);
            part[j] += __shfl_xor_sync(0xffffffffu, part[j], 2);
        }
        __syncthreads();   // prior tile's red reads complete before overwrite
        if ((l & 3) == 0) {
            #pragma unroll
            for (int j = 0; j < 8; j++) {
                int row = wm * 64 + (j >> 1) * 16 + (l >> 2) + (j & 1) * 8;
                red[row * 8 + wn] = part[j];
            }
        }
        __syncthreads();

        if (tid < 128) {
            float rPr = 0.0f;
            #pragma unroll
            for (int j = 0; j < 8; j++)
                rPr += red[tid * 8 + j];
            // tq = r . v_c  (fp32, g_v broadcast -> L1)
            const float4* rr = (const float4*)(g_norm + (size_t)(s0 + tid) * F_TOT);
            const float4* vv = (const float4*)(g_v + (size_t)c * F_TOT);
            float tq = 0.0f;
            #pragma unroll 8
            for (int g4 = 0; g4 < 64; g4++) {
                float4 a = rr[g4], bq = __ldg(vv + g4);
                tq += a.x * bq.x + a.y * bq.y + a.z * bq.z + a.w * bq.w;
            }
            float cst = g_cst[c];
            float d4  = tq * tq - rPr * (2.0f * cst);
            float aqv = (-tq + sqrtf(d4)) / rPr;
            float al  = -cst / tq;
            float mu  = (fabsf(rPr) <= 1e-12f) ? al : aqv;
            unsigned bits = (mu >= 0.0f) ? __float_as_uint(mu) : 0x7f800000u;
            atomicMin(&g_mu[s0 + tid], bits);
        }
    }
}

// ---------------- final projection ------------------------------------------
__global__ void k_final(const float* __restrict__ point,
                        float* __restrict__ out)
{
    int idx = blockIdx.x * 256 + threadIdx.x;
    int s = idx >> 8;
    int f = idx & 255;
    float maxlen = __uint_as_float(g_mu[s]);
    float ls = fminf(g_len[s], maxlen);
    out[idx] = point[f] + ls * g_norm[idx];
}

// ---------------- launch ----------------------------------------------------
extern "C" void kernel_launch(void* const* d_in, const int* in_sizes, int n_in,
                              void* d_out, int out_size)
{
    const float* zs = (const float*)d_in[0];
    const float* P  = (const float*)d_in[1];
    const float* q  = (const float*)d_in[2];
    const float* b  = (const float*)d_in[3];
    const float* pt = (const float*)d_in[4];
    float* out = (float*)d_out;

    k_norm<<<S_TOT / 8, 256>>>(zs, pt);
    k_cvtP<<<(C_TOT * F_TOT * F_TOT) / 4 / 256, 256>>>(P);
    k_pre <<<C_TOT, 256>>>(P, q, b, pt);

    cudaFuncSetAttribute(k_mma, cudaFuncAttributeMaxDynamicSharedMemorySize,
                         SMEM_MMA);
    k_mma<<<dim3(1024), 512, SMEM_MMA>>>();

    k_final<<<(S_TOT * F_TOT) / 256, 256>>>(pt, out);
}

// round 12
// speedup vs baseline: 1.4332x; 1.4332x over previous
#include <cuda_runtime.h>
#include <cuda_fp16.h>
#include <math.h>
#include <stdint.h>

// Problem shape (fixed by the dataset)
#define S_TOT 4096
#define C_TOT 64
#define F_TOT 256

// ---------------- scratch (device globals: no allocation allowed) ----------
__device__ float  g_norm[S_TOT * F_TOT];   // normalized rays r[s][f] (fp32)
__device__ float  g_len [S_TOT];           // ray lengths
__device__ unsigned g_mu[S_TOT];           // min over c of mu_pos (float bits)
__device__ float  g_v   [C_TOT * F_TOT];   // v_c = P_c t + q_c
__device__ float  g_cst [C_TOT];           // q.t + 0.5 tPt - b
__device__ __half g_Rh  [S_TOT * F_TOT];   // fp16 rays
__device__ __half g_Ph  [C_TOT * F_TOT * F_TOT];  // fp16 P

// ---------------- PTX helpers (sm_80-era only: valid on plain sm_100) -------
__device__ __forceinline__ uint32_t smem_u32(const void* p) {
    uint32_t a;
    asm("{ .reg .u64 t; cvta.to.shared.u64 t, %1; cvt.u32.u64 %0, t; }"
        : "=r"(a) : "l"(p));
    return a;
}

__device__ __forceinline__ void ldsm_x4(uint32_t* r, uint32_t addr) {
    asm volatile("ldmatrix.sync.aligned.m8n8.x4.shared.b16 {%0,%1,%2,%3}, [%4];"
        : "=r"(r[0]), "=r"(r[1]), "=r"(r[2]), "=r"(r[3]) : "r"(addr));
}
__device__ __forceinline__ void mma16816(float* d, const uint32_t* a, const uint32_t* b) {
    asm volatile(
        "mma.sync.aligned.m16n8k16.row.col.f32.f16.f16.f32 "
        "{%0,%1,%2,%3}, {%4,%5,%6,%7}, {%8,%9}, {%0,%1,%2,%3};"
        : "+f"(d[0]), "+f"(d[1]), "+f"(d[2]), "+f"(d[3])
        : "r"(a[0]), "r"(a[1]), "r"(a[2]), "r"(a[3]), "r"(b[0]), "r"(b[1]));
}

#define CP_ASYNC16(dst, src) \
    asm volatile("cp.async.cg.shared.global [%0], [%1], 16;" \
                 :: "r"(dst), "l"(src) : "memory")

// ---------------- kernel 1: normalize rays, init mu, emit fp16 -------------
__global__ void k_norm(const float* __restrict__ zs,
                       const float* __restrict__ point)
{
    int warp = threadIdx.x >> 5;
    int lane = threadIdx.x & 31;
    int s = blockIdx.x * 8 + warp;

    const float4* z4 = (const float4*)(zs + (size_t)s * F_TOT);
    const float4* p4 = (const float4*)point;

    float4 a = z4[lane];
    float4 b = z4[lane + 32];
    float4 pa = p4[lane];
    float4 pb = p4[lane + 32];

    a.x -= pa.x; a.y -= pa.y; a.z -= pa.z; a.w -= pa.w;
    b.x -= pb.x; b.y -= pb.y; b.z -= pb.z; b.w -= pb.w;

    float ss = a.x*a.x + a.y*a.y + a.z*a.z + a.w*a.w
             + b.x*b.x + b.y*b.y + b.z*b.z + b.w*b.w;
    #pragma unroll
    for (int off = 16; off; off >>= 1)
        ss += __shfl_xor_sync(0xffffffffu, ss, off);

    float len = fmaxf(sqrtf(ss), 1e-12f);
    float inv = 1.0f / len;
    a.x *= inv; a.y *= inv; a.z *= inv; a.w *= inv;
    b.x *= inv; b.y *= inv; b.z *= inv; b.w *= inv;

    float4* o4 = (float4*)(g_norm + (size_t)s * F_TOT);
    o4[lane]      = a;
    o4[lane + 32] = b;

    __half2* h2 = (__half2*)(g_Rh + (size_t)s * F_TOT);
    float v[8] = {a.x, a.y, a.z, a.w, b.x, b.y, b.z, b.w};
    int base2[2] = {2 * lane, 64 + 2 * lane};
    #pragma unroll
    for (int h = 0; h < 2; h++) {
        #pragma unroll
        for (int p = 0; p < 2; p++) {
            float x = v[h*4 + p*2], y = v[h*4 + p*2 + 1];
            h2[base2[h] + p] = __halves2half2(__float2half(x), __float2half(y));
        }
    }

    if (lane == 0) {
        g_len[s] = len;
        g_mu[s]  = 0x7f800000u;   // +inf
    }
}

// ---------------- kernel: convert P to fp16 ---------------------------------
__global__ void k_cvtP(const float* __restrict__ P)
{
    size_t i = (size_t)blockIdx.x * 256 + threadIdx.x;  // float4 index
    float4 x = ((const float4*)P)[i];
    ((__half2*)g_Ph)[2*i]   = __halves2half2(__float2half(x.x), __float2half(x.y));
    ((__half2*)g_Ph)[2*i+1] = __halves2half2(__float2half(x.z), __float2half(x.w));
}

// ---------------- kernel: per-constraint precompute --------------------------
__global__ void k_pre(const float* __restrict__ P,
                      const float* __restrict__ q,
                      const float* __restrict__ b,
                      const float* __restrict__ point)
{
    int c = blockIdx.x;
    int k = threadIdx.x;

    __shared__ float t_sm[F_TOT];
    __shared__ float red1[F_TOT];
    __shared__ float red2[F_TOT];

    t_sm[k] = point[k];
    __syncthreads();

    const float* Pc = P + (size_t)c * F_TOT * F_TOT;
    float v = 0.0f;
    for (int f = 0; f < F_TOT; f++)
        v += Pc[f * F_TOT + k] * t_sm[f];

    float qk = q[c * F_TOT + k];
    float tk = t_sm[k];
    red1[k] = v  * tk;
    red2[k] = qk * tk;
    __syncthreads();
    for (int off = 128; off; off >>= 1) {
        if (k < off) { red1[k] += red1[k + off]; red2[k] += red2[k + off]; }
        __syncthreads();
    }
    g_v[c * F_TOT + k] = v + qk;
    if (k == 0)
        g_cst[c] = red2[0] + 0.5f * red1[0] - b[c];
}

// ---------------- main mma.sync kernel ---------------------------------------
// Grid (32, 64): 128-sample tile x constraint. 512 threads = 16 warps, 2(m)x8(n).
// Warp tile 64(s) x 32(f). acc[4 mtile][4 ntile][4] fp32 (64 regs).
// SINGLE fp16 pass: W = Rh . Ph, 4 K=64 chunks. rPr = sum_f W[s,f]*r[s,f].
//
// A (Rh, 64KB total) is smem-resident: all 4 chunks loaded in the first
// commit group. B: 3 rotating 32KB slots (slot i%3), distance-2 prefetch,
// wait_group 1, one barrier per chunk (R6-proven schedule).
//
// SMEM: red @0 (4KB), A @4096 (4x16KB), B @69632 (3x32KB). Total 164KB.
#define OFF_RED 0
#define OFF_A   4096
#define OFF_B   69632
#define SMEM_MMA 167936

__global__ void __launch_bounds__(512, 1) k_mma()
{
    extern __shared__ __align__(1024) char smem[];
    uint32_t sb = smem_u32(smem);
    int tid = threadIdx.x;
    int l   = tid & 31;
    int w   = tid >> 5;
    int wm  = w & 1;        // sample group (64 rows)
    int wn  = w >> 1;       // f group (32 cols)
    int s0  = blockIdx.x * 128;
    int c   = blockIdx.y;

    auto issue_B = [&](int i) {
        int k0 = i * 64;
        uint32_t bb = sb + OFF_B + (i % 3) * 32768;
        #pragma unroll
        for (int it = 0; it < 4; it++) {         // B: 256 rows x 8 x 16B
            int idx = it * 512 + tid;
            int row = idx >> 3, u = idx & 7;
            const char* src = (const char*)(g_Ph + ((size_t)c * F_TOT + row) * F_TOT + k0 + u * 8);
            CP_ASYNC16(bb + row * 128 + (((u ^ (row & 7))) << 4), src);
        }
        asm volatile("cp.async.commit_group;" ::: "memory");
    };

    // commit group 0: ALL of A (4 chunks x 128 rows x 8 x 16B = 8/thread) + B0
    {
        #pragma unroll
        for (int ch = 0; ch < 4; ch++) {
            uint32_t ab = sb + OFF_A + ch * 16384;
            int k0 = ch * 64;
            #pragma unroll
            for (int it = 0; it < 2; it++) {
                int idx = it * 512 + tid;
                int row = idx >> 3, u = idx & 7;
                const char* src = (const char*)(g_Rh + (size_t)(s0 + row) * F_TOT + k0 + u * 8);
                CP_ASYNC16(ab + row * 128 + (((u ^ (row & 7))) << 4), src);
            }
        }
        int k0 = 0;
        uint32_t bb = sb + OFF_B;
        #pragma unroll
        for (int it = 0; it < 4; it++) {
            int idx = it * 512 + tid;
            int row = idx >> 3, u = idx & 7;
            const char* src = (const char*)(g_Ph + ((size_t)c * F_TOT + row) * F_TOT + k0 + u * 8);
            CP_ASYNC16(bb + row * 128 + (((u ^ (row & 7))) << 4), src);
        }
        asm volatile("cp.async.commit_group;" ::: "memory");
    }
    issue_B(1);

    float acc[4][4][4];
    #pragma unroll
    for (int mt = 0; mt < 4; mt++)
        #pragma unroll
        for (int nt = 0; nt < 4; nt++)
            #pragma unroll
            for (int j = 0; j < 4; j++)
                acc[mt][nt][j] = 0.0f;

    // lane-invariant ldmatrix addressing
    int xr = l & 7;             // row & 7
    int aq = (l >> 3) & 1;      // A x4: matrices 1,3 rows +8
    int uq = (l >> 4) & 1;      // A x4: matrices 2,3 k-unit +1
    int ub = (l >> 3) & 1;      // B x4: matrices 1,3 k-unit +1
    int bg = (l >> 4) & 1;      // B x4: matrices 2,3 rows +8 (next n-tile)

    for (int i = 0; i < 4; i++) {
        if (i < 3) asm volatile("cp.async.wait_group 1;" ::: "memory");
        else       asm volatile("cp.async.wait_group 0;" ::: "memory");
        __syncthreads();
        if (i + 2 < 4) issue_B(i + 2);   // overlaps compute of chunk i

        uint32_t ab = sb + OFF_A + i * 16384;
        uint32_t bb = sb + OFF_B + (i % 3) * 32768;
        uint32_t aAddr = ab + (wm * 64 + aq * 8 + xr) * 128;   // + mt*16*128
        uint32_t bAddr = bb + (wn * 32 + bg * 8 + xr) * 128;   // + p*16*128

        #pragma unroll
        for (int ks = 0; ks < 4; ks++) {
            int u0 = ks * 2;
            uint32_t swzA = ((uint32_t)((u0 + uq) ^ xr)) << 4;
            uint32_t swzB = ((uint32_t)((u0 + ub) ^ xr)) << 4;
            uint32_t afr[4][4];
            #pragma unroll
            for (int mt = 0; mt < 4; mt++)
                ldsm_x4(afr[mt], aAddr + mt * 2048 + swzA);
            #pragma unroll
            for (int p = 0; p < 2; p++) {
                uint32_t bfr[4];                 // n-tiles 2p, 2p+1
                ldsm_x4(bfr, bAddr + p * 2048 + swzB);
                #pragma unroll
                for (int mt = 0; mt < 4; mt++) {
                    mma16816(acc[mt][2*p],     afr[mt], bfr);
                    mma16816(acc[mt][2*p + 1], afr[mt], bfr + 2);
                }
            }
        }
    }

    // ---- epilogue: rPr[s] = sum_f W[s,f] * r[s,f] ----------------------------
    float part[8];
    #pragma unroll
    for (int mt = 0; mt < 4; mt++) {
        #pragma unroll
        for (int half = 0; half < 2; half++) {
            int row = wm * 64 + mt * 16 + (l >> 2) + half * 8;
            const float* rrow = g_norm + (size_t)(s0 + row) * F_TOT;
            float p = 0.0f;
            #pragma unroll
            for (int nt = 0; nt < 4; nt++) {
                int f = wn * 32 + nt * 8 + (l & 3) * 2;
                float2 rv = *(const float2*)(rrow + f);
                p += acc[mt][nt][half * 2 + 0] * rv.x
                   + acc[mt][nt][half * 2 + 1] * rv.y;
            }
            part[mt * 2 + half] = p;
        }
    }
    #pragma unroll
    for (int j = 0; j < 8; j++) {
        part[j] += __shfl_xor_sync(0xffffffffu, part[j], 1);
        part[j] += __shfl_xor_sync(0xffffffffu, part[j], 2);
    }
    float* red = (float*)(smem + OFF_RED);
    __syncthreads();
    if ((l & 3) == 0) {
        #pragma unroll
        for (int j = 0; j < 8; j++) {
            int row = wm * 64 + (j >> 1) * 16 + (l >> 2) + (j & 1) * 8;
            red[row * 8 + wn] = part[j];
        }
    }
    __syncthreads();

    if (tid < 128) {
        float rPr = 0.0f;
        #pragma unroll
        for (int j = 0; j < 8; j++)
            rPr += red[tid * 8 + j];
        // tq = r . v_c  (fp32, g_v broadcast -> L1/L2 hot)
        const float4* rr = (const float4*)(g_norm + (size_t)(s0 + tid) * F_TOT);
        const float4* vv = (const float4*)(g_v + (size_t)c * F_TOT);
        float tq = 0.0f;
        #pragma unroll 8
        for (int g4 = 0; g4 < 64; g4++) {
            float4 a = rr[g4], bq = __ldg(vv + g4);
            tq += a.x * bq.x + a.y * bq.y + a.z * bq.z + a.w * bq.w;
        }
        float cst = g_cst[c];
        float d4  = tq * tq - rPr * (2.0f * cst);
        float aqv = (-tq + sqrtf(d4)) / rPr;
        float al  = -cst / tq;
        float mu  = (fabsf(rPr) <= 1e-12f) ? al : aqv;
        unsigned bits = (mu >= 0.0f) ? __float_as_uint(mu) : 0x7f800000u;
        atomicMin(&g_mu[s0 + tid], bits);
    }
}

// ---------------- final projection ------------------------------------------
__global__ void k_final(const float* __restrict__ point,
                        float* __restrict__ out)
{
    int idx = blockIdx.x * 256 + threadIdx.x;
    int s = idx >> 8;
    int f = idx & 255;
    float maxlen = __uint_as_float(g_mu[s]);
    float ls = fminf(g_len[s], maxlen);
    out[idx] = point[f] + ls * g_norm[idx];
}

// ---------------- launch ----------------------------------------------------
extern "C" void kernel_launch(void* const* d_in, const int* in_sizes, int n_in,
                              void* d_out, int out_size)
{
    const float* zs = (const float*)d_in[0];
    const float* P  = (const float*)d_in[1];
    const float* q  = (const float*)d_in[2];
    const float* b  = (const float*)d_in[3];
    const float* pt = (const float*)d_in[4];
    float* out = (float*)d_out;

    k_norm<<<S_TOT / 8, 256>>>(zs, pt);
    k_cvtP<<<(C_TOT * F_TOT * F_TOT) / 4 / 256, 256>>>(P);
    k_pre <<<C_TOT, 256>>>(P, q, b, pt);

    cudaFuncSetAttribute(k_mma, cudaFuncAttributeMaxDynamicSharedMemorySize,
                         SMEM_MMA);
    k_mma<<<dim3(S_TOT / 128, C_TOT), 512, SMEM_MMA>>>();

    k_final<<<(S_TOT * F_TOT) / 256, 256>>>(pt, out);
}

// round 13
// speedup vs baseline: 1.4625x; 1.0204x over previous
#include <cuda_runtime.h>
#include <cuda_fp16.h>
#include <math.h>
#include <stdint.h>

// Problem shape (fixed by the dataset)
#define S_TOT 4096
#define C_TOT 64
#define F_TOT 256

// ---------------- scratch (device globals: no allocation allowed) ----------
__device__ float  g_norm[S_TOT * F_TOT];   // normalized rays r[s][f] (fp32)
__device__ float  g_len [S_TOT];           // ray lengths
__device__ unsigned g_mu[S_TOT];           // min over c of mu_pos (float bits)
__device__ float  g_v   [C_TOT * F_TOT];   // v_c = P_c t + q_c
__device__ float  g_cst [C_TOT];           // q.t + 0.5 tPt - b
__device__ __half g_Rh  [S_TOT * F_TOT];   // fp16 rays
__device__ __half g_Ph  [C_TOT * F_TOT * F_TOT];  // fp16 P

// ---------------- PTX helpers (sm_80-era only: valid on plain sm_100) -------
__device__ __forceinline__ uint32_t smem_u32(const void* p) {
    uint32_t a;
    asm("{ .reg .u64 t; cvta.to.shared.u64 t, %1; cvt.u32.u64 %0, t; }"
        : "=r"(a) : "l"(p));
    return a;
}

__device__ __forceinline__ void ldsm_x4(uint32_t* r, uint32_t addr) {
    asm volatile("ldmatrix.sync.aligned.m8n8.x4.shared.b16 {%0,%1,%2,%3}, [%4];"
        : "=r"(r[0]), "=r"(r[1]), "=r"(r[2]), "=r"(r[3]) : "r"(addr));
}
__device__ __forceinline__ void mma16816(float* d, const uint32_t* a, const uint32_t* b) {
    asm volatile(
        "mma.sync.aligned.m16n8k16.row.col.f32.f16.f16.f32 "
        "{%0,%1,%2,%3}, {%4,%5,%6,%7}, {%8,%9}, {%0,%1,%2,%3};"
        : "+f"(d[0]), "+f"(d[1]), "+f"(d[2]), "+f"(d[3])
        : "r"(a[0]), "r"(a[1]), "r"(a[2]), "r"(a[3]), "r"(b[0]), "r"(b[1]));
}

#define CP_ASYNC16(dst, src) \
    asm volatile("cp.async.cg.shared.global [%0], [%1], 16;" \
                 :: "r"(dst), "l"(src) : "memory")

// ---------------- kernel 1: normalize rays, init mu, emit fp16 -------------
__global__ void k_norm(const float* __restrict__ zs,
                       const float* __restrict__ point)
{
    int warp = threadIdx.x >> 5;
    int lane = threadIdx.x & 31;
    int s = blockIdx.x * 8 + warp;

    const float4* z4 = (const float4*)(zs + (size_t)s * F_TOT);
    const float4* p4 = (const float4*)point;

    float4 a = z4[lane];
    float4 b = z4[lane + 32];
    float4 pa = p4[lane];
    float4 pb = p4[lane + 32];

    a.x -= pa.x; a.y -= pa.y; a.z -= pa.z; a.w -= pa.w;
    b.x -= pb.x; b.y -= pb.y; b.z -= pb.z; b.w -= pb.w;

    float ss = a.x*a.x + a.y*a.y + a.z*a.z + a.w*a.w
             + b.x*b.x + b.y*b.y + b.z*b.z + b.w*b.w;
    #pragma unroll
    for (int off = 16; off; off >>= 1)
        ss += __shfl_xor_sync(0xffffffffu, ss, off);

    float len = fmaxf(sqrtf(ss), 1e-12f);
    float inv = 1.0f / len;
    a.x *= inv; a.y *= inv; a.z *= inv; a.w *= inv;
    b.x *= inv; b.y *= inv; b.z *= inv; b.w *= inv;

    float4* o4 = (float4*)(g_norm + (size_t)s * F_TOT);
    o4[lane]      = a;
    o4[lane + 32] = b;

    __half2* h2 = (__half2*)(g_Rh + (size_t)s * F_TOT);
    float v[8] = {a.x, a.y, a.z, a.w, b.x, b.y, b.z, b.w};
    int base2[2] = {2 * lane, 64 + 2 * lane};
    #pragma unroll
    for (int h = 0; h < 2; h++) {
        #pragma unroll
        for (int p = 0; p < 2; p++) {
            float x = v[h*4 + p*2], y = v[h*4 + p*2 + 1];
            h2[base2[h] + p] = __halves2half2(__float2half(x), __float2half(y));
        }
    }

    if (lane == 0) {
        g_len[s] = len;
        g_mu[s]  = 0x7f800000u;   // +inf
    }
}

// ---------------- kernel: convert P to fp16 ---------------------------------
__global__ void k_cvtP(const float* __restrict__ P)
{
    size_t i = (size_t)blockIdx.x * 256 + threadIdx.x;  // float4 index
    float4 x = ((const float4*)P)[i];
    ((__half2*)g_Ph)[2*i]   = __halves2half2(__float2half(x.x), __float2half(x.y));
    ((__half2*)g_Ph)[2*i+1] = __halves2half2(__float2half(x.z), __float2half(x.w));
}

// ---------------- kernel: per-constraint precompute --------------------------
__global__ void k_pre(const float* __restrict__ P,
                      const float* __restrict__ q,
                      const float* __restrict__ b,
                      const float* __restrict__ point)
{
    int c = blockIdx.x;
    int k = threadIdx.x;

    __shared__ float t_sm[F_TOT];
    __shared__ float red1[F_TOT];
    __shared__ float red2[F_TOT];

    t_sm[k] = point[k];
    __syncthreads();

    const float* Pc = P + (size_t)c * F_TOT * F_TOT;
    float v = 0.0f;
    for (int f = 0; f < F_TOT; f++)
        v += Pc[f * F_TOT + k] * t_sm[f];

    float qk = q[c * F_TOT + k];
    float tk = t_sm[k];
    red1[k] = v  * tk;
    red2[k] = qk * tk;
    __syncthreads();
    for (int off = 128; off; off >>= 1) {
        if (k < off) { red1[k] += red1[k + off]; red2[k] += red2[k + off]; }
        __syncthreads();
    }
    g_v[c * F_TOT + k] = v + qk;
    if (k == 0)
        g_cst[c] = red2[0] + 0.5f * red1[0] - b[c];
}

// ---------------- main mma.sync kernel ---------------------------------------
// Grid (64, 64): 64-sample tile x constraint. 256 threads = 8 warps (1m x 8n).
// Warp tile 64(s) x 32(f). acc[4 mtile][4 ntile][4] fp32 (64 regs).
// SINGLE fp16 pass: W = Rh . Ph, 4 K=64 chunks. rPr = sum_f W[s,f]*r[s,f].
//
// 2 CTAs per SM (launch_bounds(256,2), 98KB smem each): two independent
// barrier domains per SM so one CTA's waits overlap the other's compute —
// attacks the measured latency-bound profile (tensor 30%, issue 13%).
//
// A (Rh, 32KB) smem-resident, loaded with B0 in commit group 0.
// B: 2 rotating 32KB slots, wait_group 0, issue chunk i+1 right after the
// barrier (slot (i+1)%2's readers finished compute i-1 before barrier i).
//
// SMEM: red @0 (2KB), A @2048 (4x8KB), B @34816 (2x32KB). Total 98KB.
#define OFF_RED 0
#define OFF_A   2048
#define OFF_B   34816
#define SMEM_MMA 100352

__global__ void __launch_bounds__(256, 2) k_mma()
{
    extern __shared__ __align__(1024) char smem[];
    uint32_t sb = smem_u32(smem);
    int tid = threadIdx.x;
    int l   = tid & 31;
    int wn  = tid >> 5;      // f group (32 cols), 8 warps
    int s0  = blockIdx.x * 64;
    int c   = blockIdx.y;

    auto issue_B = [&](int i) {
        int k0 = i * 64;
        uint32_t bb = sb + OFF_B + (i & 1) * 32768;
        #pragma unroll
        for (int it = 0; it < 8; it++) {         // B: 256 rows x 8 x 16B
            int idx = it * 256 + tid;
            int row = idx >> 3, u = idx & 7;
            const char* src = (const char*)(g_Ph + ((size_t)c * F_TOT + row) * F_TOT + k0 + u * 8);
            CP_ASYNC16(bb + row * 128 + (((u ^ (row & 7))) << 4), src);
        }
        asm volatile("cp.async.commit_group;" ::: "memory");
    };

    // commit group 0: ALL of A (4 chunks x 64 rows x 8 x 16B) + B0
    {
        #pragma unroll
        for (int ch = 0; ch < 4; ch++) {
            uint32_t ab = sb + OFF_A + ch * 8192;
            int k0 = ch * 64;
            #pragma unroll
            for (int it = 0; it < 2; it++) {
                int idx = it * 256 + tid;
                int row = idx >> 3, u = idx & 7;
                const char* src = (const char*)(g_Rh + (size_t)(s0 + row) * F_TOT + k0 + u * 8);
                CP_ASYNC16(ab + row * 128 + (((u ^ (row & 7))) << 4), src);
            }
        }
        uint32_t bb = sb + OFF_B;
        #pragma unroll
        for (int it = 0; it < 8; it++) {
            int idx = it * 256 + tid;
            int row = idx >> 3, u = idx & 7;
            const char* src = (const char*)(g_Ph + ((size_t)c * F_TOT + row) * F_TOT + u * 8);
            CP_ASYNC16(bb + row * 128 + (((u ^ (row & 7))) << 4), src);
        }
        asm volatile("cp.async.commit_group;" ::: "memory");
    }

    float acc[4][4][4];
    #pragma unroll
    for (int mt = 0; mt < 4; mt++)
        #pragma unroll
        for (int nt = 0; nt < 4; nt++)
            #pragma unroll
            for (int j = 0; j < 4; j++)
                acc[mt][nt][j] = 0.0f;

    // lane-invariant ldmatrix addressing
    int xr = l & 7;             // row & 7
    int aq = (l >> 3) & 1;      // A x4: matrices 1,3 rows +8
    int uq = (l >> 4) & 1;      // A x4: matrices 2,3 k-unit +1
    int ub = (l >> 3) & 1;      // B x4: matrices 1,3 k-unit +1
    int bg = (l >> 4) & 1;      // B x4: matrices 2,3 rows +8 (next n-tile)

    for (int i = 0; i < 4; i++) {
        asm volatile("cp.async.wait_group 0;" ::: "memory");
        __syncthreads();
        if (i + 1 < 4) issue_B(i + 1);   // copy overlaps compute of chunk i

        uint32_t ab = sb + OFF_A + i * 8192;
        uint32_t bb = sb + OFF_B + (i & 1) * 32768;
        uint32_t aAddr = ab + (aq * 8 + xr) * 128;             // + mt*16*128
        uint32_t bAddr = bb + (wn * 32 + bg * 8 + xr) * 128;   // + p*16*128

        #pragma unroll
        for (int ks = 0; ks < 4; ks++) {
            int u0 = ks * 2;
            uint32_t swzA = ((uint32_t)((u0 + uq) ^ xr)) << 4;
            uint32_t swzB = ((uint32_t)((u0 + ub) ^ xr)) << 4;
            uint32_t afr[4][4];
            #pragma unroll
            for (int mt = 0; mt < 4; mt++)
                ldsm_x4(afr[mt], aAddr + mt * 2048 + swzA);
            #pragma unroll
            for (int p = 0; p < 2; p++) {
                uint32_t bfr[4];                 // n-tiles 2p, 2p+1
                ldsm_x4(bfr, bAddr + p * 2048 + swzB);
                #pragma unroll
                for (int mt = 0; mt < 4; mt++) {
                    mma16816(acc[mt][2*p],     afr[mt], bfr);
                    mma16816(acc[mt][2*p + 1], afr[mt], bfr + 2);
                }
            }
        }
    }

    // ---- epilogue: rPr[s] = sum_f W[s,f] * r[s,f] ----------------------------
    float part[8];
    #pragma unroll
    for (int mt = 0; mt < 4; mt++) {
        #pragma unroll
        for (int half = 0; half < 2; half++) {
            int row = mt * 16 + (l >> 2) + half * 8;
            const float* rrow = g_norm + (size_t)(s0 + row) * F_TOT;
            float p = 0.0f;
            #pragma unroll
            for (int nt = 0; nt < 4; nt++) {
                int f = wn * 32 + nt * 8 + (l & 3) * 2;
                float2 rv = *(const float2*)(rrow + f);
                p += acc[mt][nt][half * 2 + 0] * rv.x
                   + acc[mt][nt][half * 2 + 1] * rv.y;
            }
            part[mt * 2 + half] = p;
        }
    }
    #pragma unroll
    for (int j = 0; j < 8; j++) {
        part[j] += __shfl_xor_sync(0xffffffffu, part[j], 1);
        part[j] += __shfl_xor_sync(0xffffffffu, part[j], 2);
    }
    float* red = (float*)(smem + OFF_RED);
    __syncthreads();
    if ((l & 3) == 0) {
        #pragma unroll
        for (int j = 0; j < 8; j++) {
            int row = (j >> 1) * 16 + (l >> 2) + (j & 1) * 8;
            red[row * 8 + wn] = part[j];
        }
    }
    __syncthreads();

    if (tid < 64) {
        float rPr = 0.0f;
        #pragma unroll
        for (int j = 0; j < 8; j++)
            rPr += red[tid * 8 + j];
        // tq = r . v_c  (fp32, g_v broadcast -> L2/L1 hot)
        const float4* rr = (const float4*)(g_norm + (size_t)(s0 + tid) * F_TOT);
        const float4* vv = (const float4*)(g_v + (size_t)c * F_TOT);
        float tq = 0.0f;
        #pragma unroll 8
        for (int g4 = 0; g4 < 64; g4++) {
            float4 a = rr[g4], bq = __ldg(vv + g4);
            tq += a.x * bq.x + a.y * bq.y + a.z * bq.z + a.w * bq.w;
        }
        float cst = g_cst[c];
        float d4  = tq * tq - rPr * (2.0f * cst);
        float aqv = (-tq + sqrtf(d4)) / rPr;
        float al  = -cst / tq;
        float mu  = (fabsf(rPr) <= 1e-12f) ? al : aqv;
        unsigned bits = (mu >= 0.0f) ? __float_as_uint(mu) : 0x7f800000u;
        atomicMin(&g_mu[s0 + tid], bits);
    }
}

// ---------------- final projection ------------------------------------------
__global__ void k_final(const float* __restrict__ point,
                        float* __restrict__ out)
{
    int idx = blockIdx.x * 256 + threadIdx.x;
    int s = idx >> 8;
    int f = idx & 255;
    float maxlen = __uint_as_float(g_mu[s]);
    float ls = fminf(g_len[s], maxlen);
    out[idx] = point[f] + ls * g_norm[idx];
}

// ---------------- launch ----------------------------------------------------
extern "C" void kernel_launch(void* const* d_in, const int* in_sizes, int n_in,
                              void* d_out, int out_size)
{
    const float* zs = (const float*)d_in[0];
    const float* P  = (const float*)d_in[1];
    const float* q  = (const float*)d_in[2];
    const float* b  = (const float*)d_in[3];
    const float* pt = (const float*)d_in[4];
    float* out = (float*)d_out;

    k_norm<<<S_TOT / 8, 256>>>(zs, pt);
    k_cvtP<<<(C_TOT * F_TOT * F_TOT) / 4 / 256, 256>>>(P);
    k_pre <<<C_TOT, 256>>>(P, q, b, pt);

    cudaFuncSetAttribute(k_mma, cudaFuncAttributeMaxDynamicSharedMemorySize,
                         SMEM_MMA);
    k_mma<<<dim3(S_TOT / 64, C_TOT), 256, SMEM_MMA>>>();

    k_final<<<(S_TOT * F_TOT) / 256, 256>>>(pt, out);
}

// round 14
// speedup vs baseline: 2.2042x; 1.5071x over previous
#include <cuda_runtime.h>
#include <cuda_fp16.h>
#include <math.h>
#include <stdint.h>

// Problem shape (fixed by the dataset)
#define S_TOT 4096
#define C_TOT 64
#define F_TOT 256

// ---------------- scratch (device globals: no allocation allowed) ----------
__device__ float  g_norm[S_TOT * F_TOT];   // normalized rays r[s][f] (fp32, for k_final)
__device__ float  g_len [S_TOT];           // ray lengths
__device__ unsigned g_mu[S_TOT];           // min over c of mu_pos (float bits)
__device__ float  g_v   [C_TOT * F_TOT];   // v_c = P_c t + q_c
__device__ float  g_cst [C_TOT];           // q.t + 0.5 tPt - b
__device__ __half g_Rh  [S_TOT * F_TOT];   // fp16 rays
__device__ __half g_Ph  [C_TOT * F_TOT * F_TOT];  // fp16 P

// ---------------- PTX helpers (sm_80-era only: valid on plain sm_100) -------
__device__ __forceinline__ uint32_t smem_u32(const void* p) {
    uint32_t a;
    asm("{ .reg .u64 t; cvta.to.shared.u64 t, %1; cvt.u32.u64 %0, t; }"
        : "=r"(a) : "l"(p));
    return a;
}

__device__ __forceinline__ void ldsm_x4(uint32_t* r, uint32_t addr) {
    asm volatile("ldmatrix.sync.aligned.m8n8.x4.shared.b16 {%0,%1,%2,%3}, [%4];"
        : "=r"(r[0]), "=r"(r[1]), "=r"(r[2]), "=r"(r[3]) : "r"(addr));
}
__device__ __forceinline__ void mma16816(float* d, const uint32_t* a, const uint32_t* b) {
    asm volatile(
        "mma.sync.aligned.m16n8k16.row.col.f32.f16.f16.f32 "
        "{%0,%1,%2,%3}, {%4,%5,%6,%7}, {%8,%9}, {%0,%1,%2,%3};"
        : "+f"(d[0]), "+f"(d[1]), "+f"(d[2]), "+f"(d[3])
        : "r"(a[0]), "r"(a[1]), "r"(a[2]), "r"(a[3]), "r"(b[0]), "r"(b[1]));
}

#define CP_ASYNC16(dst, src) \
    asm volatile("cp.async.cg.shared.global [%0], [%1], 16;" \
                 :: "r"(dst), "l"(src) : "memory")

// ---------------- kernel 1: normalize rays, init mu, emit fp16 -------------
__global__ void k_norm(const float* __restrict__ zs,
                       const float* __restrict__ point)
{
    int warp = threadIdx.x >> 5;
    int lane = threadIdx.x & 31;
    int s = blockIdx.x * 8 + warp;

    const float4* z4 = (const float4*)(zs + (size_t)s * F_TOT);
    const float4* p4 = (const float4*)point;

    float4 a = z4[lane];
    float4 b = z4[lane + 32];
    float4 pa = p4[lane];
    float4 pb = p4[lane + 32];

    a.x -= pa.x; a.y -= pa.y; a.z -= pa.z; a.w -= pa.w;
    b.x -= pb.x; b.y -= pb.y; b.z -= pb.z; b.w -= pb.w;

    float ss = a.x*a.x + a.y*a.y + a.z*a.z + a.w*a.w
             + b.x*b.x + b.y*b.y + b.z*b.z + b.w*b.w;
    #pragma unroll
    for (int off = 16; off; off >>= 1)
        ss += __shfl_xor_sync(0xffffffffu, ss, off);

    float len = fmaxf(sqrtf(ss), 1e-12f);
    float inv = 1.0f / len;
    a.x *= inv; a.y *= inv; a.z *= inv; a.w *= inv;
    b.x *= inv; b.y *= inv; b.z *= inv; b.w *= inv;

    float4* o4 = (float4*)(g_norm + (size_t)s * F_TOT);
    o4[lane]      = a;
    o4[lane + 32] = b;

    __half2* h2 = (__half2*)(g_Rh + (size_t)s * F_TOT);
    float v[8] = {a.x, a.y, a.z, a.w, b.x, b.y, b.z, b.w};
    int base2[2] = {2 * lane, 64 + 2 * lane};
    #pragma unroll
    for (int h = 0; h < 2; h++) {
        #pragma unroll
        for (int p = 0; p < 2; p++) {
            float x = v[h*4 + p*2], y = v[h*4 + p*2 + 1];
            h2[base2[h] + p] = __halves2half2(__float2half(x), __float2half(y));
        }
    }

    if (lane == 0) {
        g_len[s] = len;
        g_mu[s]  = 0x7f800000u;   // +inf
    }
}

// ---------------- kernel: convert P to fp16 ---------------------------------
__global__ void k_cvtP(const float* __restrict__ P)
{
    size_t i = (size_t)blockIdx.x * 256 + threadIdx.x;  // float4 index
    float4 x = ((const float4*)P)[i];
    ((__half2*)g_Ph)[2*i]   = __halves2half2(__float2half(x.x), __float2half(x.y));
    ((__half2*)g_Ph)[2*i+1] = __halves2half2(__float2half(x.z), __float2half(x.w));
}

// ---------------- kernel: per-constraint precompute --------------------------
__global__ void k_pre(const float* __restrict__ P,
                      const float* __restrict__ q,
                      const float* __restrict__ b,
                      const float* __restrict__ point)
{
    int c = blockIdx.x;
    int k = threadIdx.x;

    __shared__ float t_sm[F_TOT];
    __shared__ float red1[F_TOT];
    __shared__ float red2[F_TOT];

    t_sm[k] = point[k];
    __syncthreads();

    const float* Pc = P + (size_t)c * F_TOT * F_TOT;
    float v = 0.0f;
    for (int f = 0; f < F_TOT; f++)
        v += Pc[f * F_TOT + k] * t_sm[f];

    float qk = q[c * F_TOT + k];
    float tk = t_sm[k];
    red1[k] = v  * tk;
    red2[k] = qk * tk;
    __syncthreads();
    for (int off = 128; off; off >>= 1) {
        if (k < off) { red1[k] += red1[k + off]; red2[k] += red2[k + off]; }
        __syncthreads();
    }
    g_v[c * F_TOT + k] = v + qk;
    if (k == 0)
        g_cst[c] = red2[0] + 0.5f * red1[0] - b[c];
}

// ---------------- main mma.sync kernel ---------------------------------------
// Grid (32, 64): 128-sample tile x constraint. 512 threads = 16 warps, 2(m)x8(n).
// Warp tile 64(s) x 32(f). acc[4 mtile][4 ntile][4] fp32 (64 regs).
// Single fp16 pass: W = Rh . Ph. TWO K=128 chunks (each = 2 side-by-side 64-k
// sub-blocks, so per-sub addressing is identical to the 64-k layout).
// Only 2 mainloop barriers. All copies issued up-front in 2 commit groups:
//   group 0: A (all 64KB, resident) + B chunk 0 (64KB)
//   group 1: B chunk 1 (64KB)  — streams in during chunk-0 compute.
//
// Epilogue: rPr = sum_f W[s,f] * rh[s,f] with rh read from the RESIDENT A
// smem (fp16) — zero global tail traffic; tq = rh . v_c (v from L2-hot g_v).
// (Exact symmetric quad form in rh; adds ~3e-5 error, same order as GEMM.)
//
// SMEM: red @0 (4KB), A @4096 (4x16KB), B @69632 (2x64KB). Total 196KB.
#define OFF_RED 0
#define OFF_A   4096
#define OFF_B   69632
#define SMEM_MMA 200704

__global__ void __launch_bounds__(512, 1) k_mma()
{
    extern __shared__ __align__(1024) char smem[];
    uint32_t sb = smem_u32(smem);
    int tid = threadIdx.x;
    int l   = tid & 31;
    int w   = tid >> 5;
    int wm  = w & 1;        // sample group (64 rows)
    int wn  = w >> 1;       // f group (32 cols)
    int s0  = blockIdx.x * 128;
    int c   = blockIdx.y;

    // commit group 0: ALL of A (4 sub-chunks x 128 rows x 8 x 16B) + B chunk 0
    {
        #pragma unroll
        for (int ch = 0; ch < 4; ch++) {
            uint32_t ab = sb + OFF_A + ch * 16384;
            int k0 = ch * 64;
            #pragma unroll
            for (int it = 0; it < 2; it++) {
                int idx = it * 512 + tid;
                int row = idx >> 3, u = idx & 7;
                const char* src = (const char*)(g_Rh + (size_t)(s0 + row) * F_TOT + k0 + u * 8);
                CP_ASYNC16(ab + row * 128 + (((u ^ (row & 7))) << 4), src);
            }
        }
        #pragma unroll
        for (int sub = 0; sub < 2; sub++) {
            int k0 = sub * 64;
            uint32_t bb = sb + OFF_B + sub * 32768;
            #pragma unroll
            for (int it = 0; it < 4; it++) {     // 256 rows x 8 x 16B
                int idx = it * 512 + tid;
                int row = idx >> 3, u = idx & 7;
                const char* src = (const char*)(g_Ph + ((size_t)c * F_TOT + row) * F_TOT + k0 + u * 8);
                CP_ASYNC16(bb + row * 128 + (((u ^ (row & 7))) << 4), src);
            }
        }
        asm volatile("cp.async.commit_group;" ::: "memory");
    }
    // commit group 1: B chunk 1
    {
        #pragma unroll
        for (int sub = 0; sub < 2; sub++) {
            int k0 = 128 + sub * 64;
            uint32_t bb = sb + OFF_B + 65536 + sub * 32768;
            #pragma unroll
            for (int it = 0; it < 4; it++) {
                int idx = it * 512 + tid;
                int row = idx >> 3, u = idx & 7;
                const char* src = (const char*)(g_Ph + ((size_t)c * F_TOT + row) * F_TOT + k0 + u * 8);
                CP_ASYNC16(bb + row * 128 + (((u ^ (row & 7))) << 4), src);
            }
        }
        asm volatile("cp.async.commit_group;" ::: "memory");
    }

    float acc[4][4][4];
    #pragma unroll
    for (int mt = 0; mt < 4; mt++)
        #pragma unroll
        for (int nt = 0; nt < 4; nt++)
            #pragma unroll
            for (int j = 0; j < 4; j++)
                acc[mt][nt][j] = 0.0f;

    // lane-invariant ldmatrix addressing
    int xr = l & 7;             // row & 7
    int aq = (l >> 3) & 1;      // A x4: matrices 1,3 rows +8
    int uq = (l >> 4) & 1;      // A x4: matrices 2,3 k-unit +1
    int ub = (l >> 3) & 1;      // B x4: matrices 1,3 k-unit +1
    int bg = (l >> 4) & 1;      // B x4: matrices 2,3 rows +8 (next n-tile)

    #pragma unroll
    for (int i = 0; i < 2; i++) {
        if (i == 0) asm volatile("cp.async.wait_group 1;" ::: "memory");
        else        asm volatile("cp.async.wait_group 0;" ::: "memory");
        __syncthreads();

        #pragma unroll
        for (int sub = 0; sub < 2; sub++) {
            uint32_t ab = sb + OFF_A + (i * 2 + sub) * 16384;
            uint32_t bb = sb + OFF_B + i * 65536 + sub * 32768;
            uint32_t aAddr = ab + (wm * 64 + aq * 8 + xr) * 128;
            uint32_t bAddr = bb + (wn * 32 + bg * 8 + xr) * 128;

            #pragma unroll
            for (int ks = 0; ks < 4; ks++) {
                int u0 = ks * 2;
                uint32_t swzA = ((uint32_t)((u0 + uq) ^ xr)) << 4;
                uint32_t swzB = ((uint32_t)((u0 + ub) ^ xr)) << 4;
                uint32_t afr[4][4];
                #pragma unroll
                for (int mt = 0; mt < 4; mt++)
                    ldsm_x4(afr[mt], aAddr + mt * 2048 + swzA);
                #pragma unroll
                for (int p = 0; p < 2; p++) {
                    uint32_t bfr[4];                 // n-tiles 2p, 2p+1
                    ldsm_x4(bfr, bAddr + p * 2048 + swzB);
                    #pragma unroll
                    for (int mt = 0; mt < 4; mt++) {
                        mma16816(acc[mt][2*p],     afr[mt], bfr);
                        mma16816(acc[mt][2*p + 1], afr[mt], bfr + 2);
                    }
                }
            }
        }
    }

    // ---- epilogue: rPr[s] = sum_f W[s,f] * rh[s,f], rh from resident A smem --
    float part[8];
    #pragma unroll
    for (int mt = 0; mt < 4; mt++) {
        #pragma unroll
        for (int half = 0; half < 2; half++) {
            int row = wm * 64 + mt * 16 + (l >> 2) + half * 8;   // s-local
            float p = 0.0f;
            #pragma unroll
            for (int nt = 0; nt < 4; nt++) {
                int f = wn * 32 + nt * 8 + (l & 3) * 2;
                int ch = f >> 6;
                int u  = (f & 63) >> 3;
                const __half2 rv2 = *(const __half2*)(smem + OFF_A + ch * 16384
                                      + row * 128 + ((u ^ (row & 7)) << 4) + (f & 7) * 2);
                p += acc[mt][nt][half * 2 + 0] * __low2float(rv2)
                   + acc[mt][nt][half * 2 + 1] * __high2float(rv2);
            }
            part[mt * 2 + half] = p;
        }
    }
    #pragma unroll
    for (int j = 0; j < 8; j++) {
        part[j] += __shfl_xor_sync(0xffffffffu, part[j], 1);
        part[j] += __shfl_xor_sync(0xffffffffu, part[j], 2);
    }
    float* red = (float*)(smem + OFF_RED);
    __syncthreads();
    if ((l & 3) == 0) {
        #pragma unroll
        for (int j = 0; j < 8; j++) {
            int row = wm * 64 + (j >> 1) * 16 + (l >> 2) + (j & 1) * 8;
            red[row * 8 + wn] = part[j];
        }
    }
    __syncthreads();

    if (tid < 128) {
        float rPr = 0.0f;
        #pragma unroll
        for (int j = 0; j < 8; j++)
            rPr += red[tid * 8 + j];
        // tq = rh . v_c  (rh fp16 from resident A smem; v L2-hot broadcast)
        const float4* vv = (const float4*)(g_v + (size_t)c * F_TOT);
        float tq = 0.0f;
        #pragma unroll
        for (int ch = 0; ch < 4; ch++) {
            #pragma unroll
            for (int u = 0; u < 8; u++) {
                const __half2* hh = (const __half2*)(smem + OFF_A + ch * 16384
                                     + tid * 128 + ((u ^ (tid & 7)) << 4));
                int fb = (ch * 64 + u * 8) >> 2;        // float4 index
                float4 v0 = __ldg(vv + fb);
                float4 v1 = __ldg(vv + fb + 1);
                __half2 h0 = hh[0], h1 = hh[1], h2 = hh[2], h3 = hh[3];
                tq += __low2float(h0) * v0.x + __high2float(h0) * v0.y
                    + __low2float(h1) * v0.z + __high2float(h1) * v0.w
                    + __low2float(h2) * v1.x + __high2float(h2) * v1.y
                    + __low2float(h3) * v1.z + __high2float(h3) * v1.w;
            }
        }
        float cst = g_cst[c];
        float d4  = tq * tq - rPr * (2.0f * cst);
        float aqv = (-tq + sqrtf(d4)) / rPr;
        float al  = -cst / tq;
        float mu  = (fabsf(rPr) <= 1e-12f) ? al : aqv;
        unsigned bits = (mu >= 0.0f) ? __float_as_uint(mu) : 0x7f800000u;
        atomicMin(&g_mu[s0 + tid], bits);
    }
}

// ---------------- final projection ------------------------------------------
__global__ void k_final(const float* __restrict__ point,
                        float* __restrict__ out)
{
    int idx = blockIdx.x * 256 + threadIdx.x;
    int s = idx >> 8;
    int f = idx & 255;
    float maxlen = __uint_as_float(g_mu[s]);
    float ls = fminf(g_len[s], maxlen);
    out[idx] = point[f] + ls * g_norm[idx];
}

// ---------------- launch ----------------------------------------------------
extern "C" void kernel_launch(void* const* d_in, const int* in_sizes, int n_in,
                              void* d_out, int out_size)
{
    const float* zs = (const float*)d_in[0];
    const float* P  = (const float*)d_in[1];
    const float* q  = (const float*)d_in[2];
    const float* b  = (const float*)d_in[3];
    const float* pt = (const float*)d_in[4];
    float* out = (float*)d_out;

    k_norm<<<S_TOT / 8, 256>>>(zs, pt);
    k_cvtP<<<(C_TOT * F_TOT * F_TOT) / 4 / 256, 256>>>(P);
    k_pre <<<C_TOT, 256>>>(P, q, b, pt);

    cudaFuncSetAttribute(k_mma, cudaFuncAttributeMaxDynamicSharedMemorySize,
                         SMEM_MMA);
    k_mma<<<dim3(S_TOT / 128, C_TOT), 512, SMEM_MMA>>>();

    k_final<<<(S_TOT * F_TOT) / 256, 256>>>(pt, out);
}

// round 15
// speedup vs baseline: 2.3799x; 1.0797x over previous
#include <cuda_runtime.h>
#include <cuda_fp16.h>
#include <math.h>
#include <stdint.h>

// Problem shape (fixed by the dataset)
#define S_TOT 4096
#define C_TOT 64
#define F_TOT 256

// ---------------- scratch (device globals: no allocation allowed) ----------
__device__ float  g_norm[S_TOT * F_TOT];   // normalized rays r[s][f] (fp32, for k_final)
__device__ float  g_len [S_TOT];           // ray lengths
__device__ unsigned g_mu[S_TOT];           // min over c of mu_pos (float bits)
__device__ float  g_v   [C_TOT * F_TOT];   // v_c = P_c t + q_c
__device__ float  g_cst [C_TOT];           // q.t + 0.5 tPt - b
__device__ __half g_Rh  [S_TOT * F_TOT];   // fp16 rays
__device__ __half g_Ph  [C_TOT * F_TOT * F_TOT];  // fp16 P

// ---------------- PTX helpers (sm_80-era only: valid on plain sm_100) -------
__device__ __forceinline__ uint32_t smem_u32(const void* p) {
    uint32_t a;
    asm("{ .reg .u64 t; cvta.to.shared.u64 t, %1; cvt.u32.u64 %0, t; }"
        : "=r"(a) : "l"(p));
    return a;
}

__device__ __forceinline__ void ldsm_x4(uint32_t* r, uint32_t addr) {
    asm volatile("ldmatrix.sync.aligned.m8n8.x4.shared.b16 {%0,%1,%2,%3}, [%4];"
        : "=r"(r[0]), "=r"(r[1]), "=r"(r[2]), "=r"(r[3]) : "r"(addr));
}
__device__ __forceinline__ void mma16816(float* d, const uint32_t* a, const uint32_t* b) {
    asm volatile(
        "mma.sync.aligned.m16n8k16.row.col.f32.f16.f16.f32 "
        "{%0,%1,%2,%3}, {%4,%5,%6,%7}, {%8,%9}, {%0,%1,%2,%3};"
        : "+f"(d[0]), "+f"(d[1]), "+f"(d[2]), "+f"(d[3])
        : "r"(a[0]), "r"(a[1]), "r"(a[2]), "r"(a[3]), "r"(b[0]), "r"(b[1]));
}

#define CP_ASYNC16(dst, src) \
    asm volatile("cp.async.cg.shared.global [%0], [%1], 16;" \
                 :: "r"(dst), "l"(src) : "memory")

// ---------------- kernel 1: normalize rays, init mu, emit fp16 -------------
__global__ void k_norm(const float* __restrict__ zs,
                       const float* __restrict__ point)
{
    int warp = threadIdx.x >> 5;
    int lane = threadIdx.x & 31;
    int s = blockIdx.x * 8 + warp;

    const float4* z4 = (const float4*)(zs + (size_t)s * F_TOT);
    const float4* p4 = (const float4*)point;

    float4 a = z4[lane];
    float4 b = z4[lane + 32];
    float4 pa = p4[lane];
    float4 pb = p4[lane + 32];

    a.x -= pa.x; a.y -= pa.y; a.z -= pa.z; a.w -= pa.w;
    b.x -= pb.x; b.y -= pb.y; b.z -= pb.z; b.w -= pb.w;

    float ss = a.x*a.x + a.y*a.y + a.z*a.z + a.w*a.w
             + b.x*b.x + b.y*b.y + b.z*b.z + b.w*b.w;
    #pragma unroll
    for (int off = 16; off; off >>= 1)
        ss += __shfl_xor_sync(0xffffffffu, ss, off);

    float len = fmaxf(sqrtf(ss), 1e-12f);
    float inv = 1.0f / len;
    a.x *= inv; a.y *= inv; a.z *= inv; a.w *= inv;
    b.x *= inv; b.y *= inv; b.z *= inv; b.w *= inv;

    float4* o4 = (float4*)(g_norm + (size_t)s * F_TOT);
    o4[lane]      = a;
    o4[lane + 32] = b;

    __half2* h2 = (__half2*)(g_Rh + (size_t)s * F_TOT);
    float v[8] = {a.x, a.y, a.z, a.w, b.x, b.y, b.z, b.w};
    int base2[2] = {2 * lane, 64 + 2 * lane};
    #pragma unroll
    for (int h = 0; h < 2; h++) {
        #pragma unroll
        for (int p = 0; p < 2; p++) {
            float x = v[h*4 + p*2], y = v[h*4 + p*2 + 1];
            h2[base2[h] + p] = __halves2half2(__float2half(x), __float2half(y));
        }
    }

    if (lane == 0) {
        g_len[s] = len;
        g_mu[s]  = 0x7f800000u;   // +inf
    }
}

// ---------------- kernel: convert P to fp16 ---------------------------------
__global__ void k_cvtP(const float* __restrict__ P)
{
    size_t i = (size_t)blockIdx.x * 256 + threadIdx.x;  // float4 index
    float4 x = ((const float4*)P)[i];
    ((__half2*)g_Ph)[2*i]   = __halves2half2(__float2half(x.x), __float2half(x.y));
    ((__half2*)g_Ph)[2*i+1] = __halves2half2(__float2half(x.z), __float2half(x.w));
}

// ---------------- kernel: per-constraint precompute --------------------------
__global__ void k_pre(const float* __restrict__ P,
                      const float* __restrict__ q,
                      const float* __restrict__ b,
                      const float* __restrict__ point)
{
    int c = blockIdx.x;
    int k = threadIdx.x;

    __shared__ float t_sm[F_TOT];
    __shared__ float red1[F_TOT];
    __shared__ float red2[F_TOT];

    t_sm[k] = point[k];
    __syncthreads();

    const float* Pc = P + (size_t)c * F_TOT * F_TOT;
    float v = 0.0f;
    for (int f = 0; f < F_TOT; f++)
        v += Pc[f * F_TOT + k] * t_sm[f];

    float qk = q[c * F_TOT + k];
    float tk = t_sm[k];
    red1[k] = v  * tk;
    red2[k] = qk * tk;
    __syncthreads();
    for (int off = 128; off; off >>= 1) {
        if (k < off) { red1[k] += red1[k + off]; red2[k] += red2[k + off]; }
        __syncthreads();
    }
    g_v[c * F_TOT + k] = v + qk;
    if (k == 0)
        g_cst[c] = red2[0] + 0.5f * red1[0] - b[c];
}

// ---------------- main mma.sync kernel ---------------------------------------
// Grid (64, 64): 64-sample tile x constraint. 256 threads = 8 warps (1m x 8n).
// Warp tile 64(s) x 32(f). acc[4 mtile][4 ntile][4] fp32 (64 regs).
// Single fp16 pass: W = Rh . Ph, 4 K=64 chunks.
//
// 2 CTAs per SM (98KB smem, launch_bounds(256,2)): two independent barrier
// domains so one CTA's fill/epilogue overlaps the other CTA's MMAs — attacks
// the measured per-wave serial fill+epilogue exposure of the 1-CTA config.
//
// A (Rh, 32KB) smem-resident (group 0, with B0). B: 2 rotating 32KB slots,
// wait_group 0, B(i+1) issued after barrier i (slot (i+1)&1's readers done).
// Epilogue entirely from smem A (fp16 quad form) + L2-hot g_v.
//
// SMEM: red @0 (2KB), A @2048 (4x8KB), B @34816 (2x32KB). Total 98KB.
#define OFF_RED 0
#define OFF_A   2048
#define OFF_B   34816
#define SMEM_MMA 100352

__global__ void __launch_bounds__(256, 2) k_mma()
{
    extern __shared__ __align__(1024) char smem[];
    uint32_t sb = smem_u32(smem);
    int tid = threadIdx.x;
    int l   = tid & 31;
    int wn  = tid >> 5;      // f group (32 cols), 8 warps
    int s0  = blockIdx.x * 64;
    int c   = blockIdx.y;

    auto issue_B = [&](int i) {
        int k0 = i * 64;
        uint32_t bb = sb + OFF_B + (i & 1) * 32768;
        #pragma unroll
        for (int it = 0; it < 8; it++) {         // B: 256 rows x 8 x 16B
            int idx = it * 256 + tid;
            int row = idx >> 3, u = idx & 7;
            const char* src = (const char*)(g_Ph + ((size_t)c * F_TOT + row) * F_TOT + k0 + u * 8);
            CP_ASYNC16(bb + row * 128 + (((u ^ (row & 7))) << 4), src);
        }
        asm volatile("cp.async.commit_group;" ::: "memory");
    };

    // commit group 0: ALL of A (4 chunks x 64 rows x 8 x 16B) + B0
    {
        #pragma unroll
        for (int ch = 0; ch < 4; ch++) {
            uint32_t ab = sb + OFF_A + ch * 8192;
            int k0 = ch * 64;
            #pragma unroll
            for (int it = 0; it < 2; it++) {
                int idx = it * 256 + tid;
                int row = idx >> 3, u = idx & 7;
                const char* src = (const char*)(g_Rh + (size_t)(s0 + row) * F_TOT + k0 + u * 8);
                CP_ASYNC16(ab + row * 128 + (((u ^ (row & 7))) << 4), src);
            }
        }
        uint32_t bb = sb + OFF_B;
        #pragma unroll
        for (int it = 0; it < 8; it++) {
            int idx = it * 256 + tid;
            int row = idx >> 3, u = idx & 7;
            const char* src = (const char*)(g_Ph + ((size_t)c * F_TOT + row) * F_TOT + u * 8);
            CP_ASYNC16(bb + row * 128 + (((u ^ (row & 7))) << 4), src);
        }
        asm volatile("cp.async.commit_group;" ::: "memory");
    }

    float acc[4][4][4];
    #pragma unroll
    for (int mt = 0; mt < 4; mt++)
        #pragma unroll
        for (int nt = 0; nt < 4; nt++)
            #pragma unroll
            for (int j = 0; j < 4; j++)
                acc[mt][nt][j] = 0.0f;

    // lane-invariant ldmatrix addressing
    int xr = l & 7;             // row & 7
    int aq = (l >> 3) & 1;      // A x4: matrices 1,3 rows +8
    int uq = (l >> 4) & 1;      // A x4: matrices 2,3 k-unit +1
    int ub = (l >> 3) & 1;      // B x4: matrices 1,3 k-unit +1
    int bg = (l >> 4) & 1;      // B x4: matrices 2,3 rows +8 (next n-tile)

    for (int i = 0; i < 4; i++) {
        asm volatile("cp.async.wait_group 0;" ::: "memory");
        __syncthreads();
        if (i + 1 < 4) issue_B(i + 1);   // copy overlaps compute of chunk i

        uint32_t ab = sb + OFF_A + i * 8192;
        uint32_t bb = sb + OFF_B + (i & 1) * 32768;
        uint32_t aAddr = ab + (aq * 8 + xr) * 128;             // + mt*16*128
        uint32_t bAddr = bb + (wn * 32 + bg * 8 + xr) * 128;   // + p*16*128

        #pragma unroll
        for (int ks = 0; ks < 4; ks++) {
            int u0 = ks * 2;
            uint32_t swzA = ((uint32_t)((u0 + uq) ^ xr)) << 4;
            uint32_t swzB = ((uint32_t)((u0 + ub) ^ xr)) << 4;
            uint32_t afr[4][4];
            #pragma unroll
            for (int mt = 0; mt < 4; mt++)
                ldsm_x4(afr[mt], aAddr + mt * 2048 + swzA);
            #pragma unroll
            for (int p = 0; p < 2; p++) {
                uint32_t bfr[4];                 // n-tiles 2p, 2p+1
                ldsm_x4(bfr, bAddr + p * 2048 + swzB);
                #pragma unroll
                for (int mt = 0; mt < 4; mt++) {
                    mma16816(acc[mt][2*p],     afr[mt], bfr);
                    mma16816(acc[mt][2*p + 1], afr[mt], bfr + 2);
                }
            }
        }
    }

    // ---- epilogue: rPr[s] = sum_f W[s,f] * rh[s,f], rh from resident A smem --
    float part[8];
    #pragma unroll
    for (int mt = 0; mt < 4; mt++) {
        #pragma unroll
        for (int half = 0; half < 2; half++) {
            int row = mt * 16 + (l >> 2) + half * 8;   // 0..63
            float p = 0.0f;
            #pragma unroll
            for (int nt = 0; nt < 4; nt++) {
                int f = wn * 32 + nt * 8 + (l & 3) * 2;
                int ch = f >> 6;
                int u  = (f & 63) >> 3;
                const __half2 rv2 = *(const __half2*)(smem + OFF_A + ch * 8192
                                      + row * 128 + ((u ^ (row & 7)) << 4) + (f & 7) * 2);
                p += acc[mt][nt][half * 2 + 0] * __low2float(rv2)
                   + acc[mt][nt][half * 2 + 1] * __high2float(rv2);
            }
            part[mt * 2 + half] = p;
        }
    }
    #pragma unroll
    for (int j = 0; j < 8; j++) {
        part[j] += __shfl_xor_sync(0xffffffffu, part[j], 1);
        part[j] += __shfl_xor_sync(0xffffffffu, part[j], 2);
    }
    float* red = (float*)(smem + OFF_RED);
    __syncthreads();
    if ((l & 3) == 0) {
        #pragma unroll
        for (int j = 0; j < 8; j++) {
            int row = (j >> 1) * 16 + (l >> 2) + (j & 1) * 8;
            red[row * 8 + wn] = part[j];
        }
    }
    __syncthreads();

    if (tid < 64) {
        float rPr = 0.0f;
        #pragma unroll
        for (int j = 0; j < 8; j++)
            rPr += red[tid * 8 + j];
        // tq = rh . v_c  (rh fp16 from resident A smem; v L2-hot broadcast)
        const float4* vv = (const float4*)(g_v + (size_t)c * F_TOT);
        float tq = 0.0f;
        #pragma unroll
        for (int ch = 0; ch < 4; ch++) {
            #pragma unroll
            for (int u = 0; u < 8; u++) {
                const __half2* hh = (const __half2*)(smem + OFF_A + ch * 8192
                                     + tid * 128 + ((u ^ (tid & 7)) << 4));
                int fb = (ch * 64 + u * 8) >> 2;        // float4 index
                float4 v0 = __ldg(vv + fb);
                float4 v1 = __ldg(vv + fb + 1);
                __half2 h0 = hh[0], h1 = hh[1], h2 = hh[2], h3 = hh[3];
                tq += __low2float(h0) * v0.x + __high2float(h0) * v0.y
                    + __low2float(h1) * v0.z + __high2float(h1) * v0.w
                    + __low2float(h2) * v1.x + __high2float(h2) * v1.y
                    + __low2float(h3) * v1.z + __high2float(h3) * v1.w;
            }
        }
        float cst = g_cst[c];
        float d4  = tq * tq - rPr * (2.0f * cst);
        float aqv = (-tq + sqrtf(d4)) / rPr;
        float al  = -cst / tq;
        float mu  = (fabsf(rPr) <= 1e-12f) ? al : aqv;
        unsigned bits = (mu >= 0.0f) ? __float_as_uint(mu) : 0x7f800000u;
        atomicMin(&g_mu[s0 + tid], bits);
    }
}

// ---------------- final projection ------------------------------------------
__global__ void k_final(const float* __restrict__ point,
                        float* __restrict__ out)
{
    int idx = blockIdx.x * 256 + threadIdx.x;
    int s = idx >> 8;
    int f = idx & 255;
    float maxlen = __uint_as_float(g_mu[s]);
    float ls = fminf(g_len[s], maxlen);
    out[idx] = point[f] + ls * g_norm[idx];
}

// ---------------- launch ----------------------------------------------------
extern "C" void kernel_launch(void* const* d_in, const int* in_sizes, int n_in,
                              void* d_out, int out_size)
{
    const float* zs = (const float*)d_in[0];
    const float* P  = (const float*)d_in[1];
    const float* q  = (const float*)d_in[2];
    const float* b  = (const float*)d_in[3];
    const float* pt = (const float*)d_in[4];
    float* out = (float*)d_out;

    k_norm<<<S_TOT / 8, 256>>>(zs, pt);
    k_cvtP<<<(C_TOT * F_TOT * F_TOT) / 4 / 256, 256>>>(P);
    k_pre <<<C_TOT, 256>>>(P, q, b, pt);

    cudaFuncSetAttribute(k_mma, cudaFuncAttributeMaxDynamicSharedMemorySize,
                         SMEM_MMA);
    k_mma<<<dim3(S_TOT / 64, C_TOT), 256, SMEM_MMA>>>();

    k_final<<<(S_TOT * F_TOT) / 256, 256>>>(pt, out);
}